// round 13
// baseline (speedup 1.0000x reference)
#include <cuda_runtime.h>
#include <cuda_fp16.h>
#include <cstdint>
#include <math.h>

// ---------------------------------------------------------------------------
// Problem constants
// ---------------------------------------------------------------------------
#define B_     4096
#define NIN    2048
#define NOUT   2048
#define KTOT   4096              // NIN + NOUT
#define NTOT   8192              // 4 * NOUT

// GEMM tiling: 128(M) x 128(N-packed) x 64(K), 256 threads, 8 warps (4m x 2n),
// warp tile 32x64, 2 CTAs/SM, in-place software-pipelined fragment loads.
#define BM     128
#define BN     128
#define BK     64
#define STG    3
#define A_STAGE_B  (BM * BK * 2)             // 16384
#define B_STAGE_B  (BN * BK * 2)             // 16384
#define STAGE_B    (A_STAGE_B + B_STAGE_B)   // 32768
#define SMEM_TOTAL (STG * STAGE_B)           // 98304 -> 2 CTAs/SM
#define EPI_PITCH  132                        // fp32 words per row (128 + 4 pad)

// ---------------------------------------------------------------------------
// Device scratch (static; no allocation allowed)
// ---------------------------------------------------------------------------
__device__ __align__(16) __half g_Th[(size_t)B_ * KTOT];     // 32 MB
__device__ __align__(16) __half g_Wh[(size_t)NTOT * KTOT];   // 64 MB (rows: j*4+gate)

// ---------------------------------------------------------------------------
// Helpers
// ---------------------------------------------------------------------------
__device__ __forceinline__ uint32_t smem_u32(const void* p) {
    uint32_t a;
    asm("{ .reg .u64 t; cvta.to.shared.u64 t, %1; cvt.u32.u64 %0, t; }" : "=r"(a) : "l"(p));
    return a;
}

__device__ __forceinline__ void cp16(uint32_t dst, const void* src) {
    asm volatile("cp.async.cg.shared.global [%0], [%1], 16;" :: "r"(dst), "l"(src));
}

__device__ __forceinline__ void ldsm4(uint32_t* d, uint32_t addr) {
    asm volatile("ldmatrix.sync.aligned.m8n8.x4.shared.b16 {%0,%1,%2,%3}, [%4];"
                 : "=r"(d[0]), "=r"(d[1]), "=r"(d[2]), "=r"(d[3]) : "r"(addr));
}

__device__ __forceinline__ void mma16816(float* c,
                                         uint32_t a0, uint32_t a1, uint32_t a2, uint32_t a3,
                                         uint32_t b0, uint32_t b1) {
    asm volatile("mma.sync.aligned.m16n8k16.row.col.f32.f16.f16.f32 "
                 "{%0,%1,%2,%3}, {%4,%5,%6,%7}, {%8,%9}, {%0,%1,%2,%3};"
                 : "+f"(c[0]), "+f"(c[1]), "+f"(c[2]), "+f"(c[3])
                 : "r"(a0), "r"(a1), "r"(a2), "r"(a3), "r"(b0), "r"(b1));
}

__device__ __forceinline__ float sigmoidf_(float z) { return 1.0f / (1.0f + expf(-z)); }

__device__ __forceinline__ uint32_t packh2(float a, float b) {
    __half2 p = __floats2half2_rn(a, b);
    return *reinterpret_cast<uint32_t*>(&p);
}

// ---------------------------------------------------------------------------
// Fused conversion kernel: fp32 -> fp16 for both T and packed W.
// ---------------------------------------------------------------------------
__device__ __forceinline__ uint4 pack8_h(const float* src) {
    float4 v0 = *reinterpret_cast<const float4*>(src);
    float4 v1 = *reinterpret_cast<const float4*>(src + 4);
    uint4 o;
    o.x = packh2(v0.x, v0.y);
    o.y = packh2(v0.z, v0.w);
    o.z = packh2(v1.x, v1.y);
    o.w = packh2(v1.z, v1.w);
    return o;
}

#define T_BLOCKS ((B_ * 512) / 256)          // 8192
#define W_BLOCKS ((NTOT * 512) / 256)        // 16384

__global__ void __launch_bounds__(256)
conv_all_kernel(const float* __restrict__ x, const float* __restrict__ h,
                const float* __restrict__ Wf, const float* __restrict__ Wi,
                const float* __restrict__ Wo, const float* __restrict__ Wg) {
    uint32_t b = blockIdx.x;
    if (b < T_BLOCKS) {
        uint32_t idx = b * 256 + threadIdx.x;
        uint32_t m = idx >> 9;
        uint32_t k = (idx & 511) * 8;
        const float* src = (k < NIN) ? (x + (size_t)m * NIN + k)
                                     : (h + (size_t)m * NOUT + (k - NIN));
        *reinterpret_cast<uint4*>(g_Th + (size_t)m * KTOT + k) = pack8_h(src);
    } else {
        uint32_t idx = (b - T_BLOCKS) * 256 + threadIdx.x;
        uint32_t jall = idx >> 9;                 // gate*2048 + j
        uint32_t k = (idx & 511) * 8;
        uint32_t gate = jall >> 11;
        uint32_t j = jall & 2047;
        const float* W = (gate == 0) ? Wf : (gate == 1) ? Wi : (gate == 2) ? Wo : Wg;
        uint32_t p = j * 4 + gate;
        *reinterpret_cast<uint4*>(g_Wh + (size_t)p * KTOT + k) =
            pack8_h(W + (size_t)j * KTOT + k);
    }
}

// ---------------------------------------------------------------------------
// Fused GEMM + LSTM epilogue. In-place software pipeline: each fragment is
// reloaded for kk+1 immediately after its last consumer MMA of kk issues,
// hiding LDSM latency under MMA issue without extra registers. Iteration
// boundary stays race-free: wait_group -> __syncthreads -> preload kk0.
// grid = 2048 (mt = bid&31, nt = bid>>5), 256 threads, 3-stage cp.async.
// ---------------------------------------------------------------------------
__global__ void __launch_bounds__(256, 2)
lstm_gemm_fused_kernel(const float* __restrict__ c_old,
                       const float* __restrict__ bf,
                       const float* __restrict__ bi,
                       const float* __restrict__ bo,
                       const float* __restrict__ bg,
                       float* __restrict__ out) {
    extern __shared__ __align__(1024) char smem[];
    const uint32_t sbase = smem_u32(smem);

    const int t    = threadIdx.x;
    const int lane = t & 31;
    const int wid  = t >> 5;      // 0..7
    const int wm   = wid & 3;     // warp m band: 32 rows
    const int wn   = wid >> 2;    // warp n band: 64 packed cols

    const int bid = blockIdx.x;
    const int mt = bid & 31;
    const int nt = bid >> 5;
    const int m0 = mt * BM;
    const int p0 = nt * BN;       // packed col base
    const int j0 = nt * 32;       // j base

    // ---- cp.async constants
    const uint32_t xorvt  = (uint32_t)((t >> 3) & 7) << 4;
    const uint32_t dstA0  = (uint32_t)(t >> 3) * 128 + (((uint32_t)(t & 7) * 16) ^ xorvt);
    const uint32_t dstB0  = dstA0 + A_STAGE_B;
    const __half* srcA = g_Th + (size_t)(m0 + (t >> 3)) * KTOT + (t & 7) * 8;
    const __half* srcB = g_Wh + (size_t)(p0 + (t >> 3)) * KTOT + (t & 7) * 8;
    int kptr = 0;   // element offset bumped by BK per fill

    const uint32_t stg0 = sbase;
    const uint32_t stg1 = sbase + STAGE_B;
    const uint32_t stg2 = sbase + 2 * STAGE_B;

    // ---- LDSM constants: addr = stage + rowterm[f] + kxv[kk]
    const uint32_t lrow  = (uint32_t)(lane & 15);
    const uint32_t lkofb = (lane & 16) ? 16u : 0u;
    const uint32_t xorv  = (uint32_t)(lane & 7) << 4;
    uint32_t rowA[2], rowB[4], kxv[4];
#pragma unroll
    for (int mf = 0; mf < 2; mf++)
        rowA[mf] = (uint32_t)(wm * 32 + mf * 16 + lrow) * 128;
#pragma unroll
    for (int nf = 0; nf < 4; nf++)
        rowB[nf] = A_STAGE_B + (uint32_t)(wn * 64 + nf * 16 + lrow) * 128;
#pragma unroll
    for (int kk = 0; kk < 4; kk++)
        kxv[kk] = ((uint32_t)(kk * 32) + lkofb) ^ xorv;

    float acc[2][8][4];           // [mf][n8][quad]
#pragma unroll
    for (int i = 0; i < 2; i++)
#pragma unroll
        for (int j = 0; j < 8; j++)
#pragma unroll
            for (int q = 0; q < 4; q++) acc[i][j][q] = 0.0f;

    uint32_t a[2][4], b[4][4];

    auto fill_stage = [&](uint32_t stg) {
        const __half* sa = srcA + kptr;
        const __half* sb = srcB + kptr;
#pragma unroll
        for (int i = 0; i < 4; i++)
            cp16(stg + dstA0 + i * 4096, sa + (size_t)i * 32 * KTOT);
#pragma unroll
        for (int i = 0; i < 4; i++)
            cp16(stg + dstB0 + i * 4096, sb + (size_t)i * 32 * KTOT);
        asm volatile("cp.async.commit_group;" ::: "memory");
        kptr += BK;
    };

    auto load_kk = [&](uint32_t stg, int kk) {
        const uint32_t kx = kxv[kk];
#pragma unroll
        for (int mf = 0; mf < 2; mf++)
            ldsm4(a[mf], stg + rowA[mf] + kx);
#pragma unroll
        for (int nf = 0; nf < 4; nf++)
            ldsm4(b[nf], stg + rowB[nf] + kx);
    };

    // ---- prologue: two stages in flight; wait -> BARRIER -> preload kk0
    fill_stage(stg0);
    fill_stage(stg1);
    asm volatile("cp.async.wait_group 1;" ::: "memory");
    __syncthreads();
    load_kk(stg0, 0);

    const int NIT = KTOT / BK;     // 64
    uint32_t stg_cur = stg0, stg_nxt = stg1, stg_fill = stg2;

    for (int it = 0; it < NIT; it++) {
        // fill(it+2): buffer released by barrier at end of it-1; issue
        // overlaps kk0's MMAs.
        if (it + 2 < NIT)
            fill_stage(stg_fill);

#pragma unroll
        for (int kk = 0; kk < 4; kk++) {
            // a[0] half: 8 MMAs, then retire a[0] and reload it for kk+1
#pragma unroll
            for (int nf = 0; nf < 4; nf++) {
                mma16816(acc[0][nf * 2],     a[0][0], a[0][1], a[0][2], a[0][3],
                         b[nf][0], b[nf][2]);
                mma16816(acc[0][nf * 2 + 1], a[0][0], a[0][1], a[0][2], a[0][3],
                         b[nf][1], b[nf][3]);
            }
            if (kk < 3)
                ldsm4(a[0], stg_cur + rowA[0] + kxv[kk + 1]);
            // a[1] half: reload each b[nf] right after its last consumer
#pragma unroll
            for (int nf = 0; nf < 4; nf++) {
                mma16816(acc[1][nf * 2],     a[1][0], a[1][1], a[1][2], a[1][3],
                         b[nf][0], b[nf][2]);
                mma16816(acc[1][nf * 2 + 1], a[1][0], a[1][1], a[1][2], a[1][3],
                         b[nf][1], b[nf][3]);
                if (kk < 3)
                    ldsm4(b[nf], stg_cur + rowB[nf] + kxv[kk + 1]);
            }
            if (kk < 3)
                ldsm4(a[1], stg_cur + rowA[1] + kxv[kk + 1]);
        }

        // boundary: per-thread wait, BARRIER, then preload next stage's kk0
        if (it + 1 < NIT) {
            if (it + 2 < NIT)
                asm volatile("cp.async.wait_group 1;" ::: "memory");
            else
                asm volatile("cp.async.wait_group 0;" ::: "memory");
            __syncthreads();
            load_kk(stg_nxt, 0);
        }

        uint32_t tmp = stg_cur;
        stg_cur = stg_nxt;
        stg_nxt = stg_fill;
        stg_fill = tmp;
    }

    // ---- drain, then reuse smem as fp32 Z tile [128][EPI_PITCH] ----
    asm volatile("cp.async.wait_group 0;" ::: "memory");
    __syncthreads();

    float* zt = reinterpret_cast<float*>(smem);
    {
        const int r0 = wm * 32 + (lane >> 2);
        const int c0 = wn * 64 + (lane & 3) * 2;
#pragma unroll
        for (int mf = 0; mf < 2; mf++) {
            int row = r0 + mf * 16;
#pragma unroll
            for (int n8 = 0; n8 < 8; n8++) {
                int pc = c0 + n8 * 8;
                *reinterpret_cast<float2*>(&zt[(size_t)row * EPI_PITCH + pc]) =
                    make_float2(acc[mf][n8][0], acc[mf][n8][1]);
                *reinterpret_cast<float2*>(&zt[(size_t)(row + 8) * EPI_PITCH + pc]) =
                    make_float2(acc[mf][n8][2], acc[mf][n8][3]);
            }
        }
    }
    __syncthreads();

    // ---- fused LSTM epilogue: warp -> 16-row block, lane -> j ----
    {
        const int j = lane;                  // 0..31
        const int jg = j0 + j;
        const float bfs = bf[jg];
        const float bis = bi[jg];
        const float bos = bo[jg];
        const float bgs = bg[jg];
#pragma unroll
        for (int i = 0; i < 16; i++) {
            int ml = wid * 16 + i;
            float4 z = *reinterpret_cast<const float4*>(&zt[(size_t)ml * EPI_PITCH + j * 4]);
            float zf = z.x + bfs;
            float zi = z.y + bis;
            float zo = z.z + bos;
            float zg = z.w + bgs;
            int m = m0 + ml;
            float co = c_old[(size_t)m * NOUT + jg];
            float f  = sigmoidf_(zf);
            float ii = sigmoidf_(zi);
            float oo = sigmoidf_(zo);
            float g  = tanhf(zg);
            float c  = f * co + ii * g;
            float hh = oo * tanhf(c);
            out[(size_t)m * NOUT + jg] = c;
            out[(size_t)B_ * NOUT + (size_t)m * NOUT + jg] = hh;
        }
    }
}

// ---------------------------------------------------------------------------
// kernel_launch
// Input order: c_old, h_old, x, Wf, bf, Wi, bi, Wo, bo, Wg, bg, mode
// ---------------------------------------------------------------------------
extern "C" void kernel_launch(void* const* d_in, const int* in_sizes, int n_in,
                              void* d_out, int out_size) {
    const float* c_old = (const float*)d_in[0];
    const float* h_old = (const float*)d_in[1];
    const float* x     = (const float*)d_in[2];
    const float* Wf    = (const float*)d_in[3];
    const float* bf    = (const float*)d_in[4];
    const float* Wi    = (const float*)d_in[5];
    const float* bi    = (const float*)d_in[6];
    const float* Wo    = (const float*)d_in[7];
    const float* bo    = (const float*)d_in[8];
    const float* Wg    = (const float*)d_in[9];
    const float* bg    = (const float*)d_in[10];
    float* out = (float*)d_out;

    static int configured = 0;
    if (!configured) {
        cudaFuncSetAttribute(lstm_gemm_fused_kernel,
                             cudaFuncAttributeMaxDynamicSharedMemorySize, SMEM_TOTAL);
        configured = 1;
    }

    conv_all_kernel<<<T_BLOCKS + W_BLOCKS, 256>>>(x, h_old, Wf, Wi, Wo, Wg);

    lstm_gemm_fused_kernel<<<(B_ / BM) * (NTOT / BN), 256, SMEM_TOTAL>>>(
        c_old, bf, bi, bo, bg, out);
}

// round 14
// speedup vs baseline: 1.1103x; 1.1103x over previous
#include <cuda_runtime.h>
#include <cuda_fp16.h>
#include <cstdint>
#include <math.h>

// ---------------------------------------------------------------------------
// Problem constants
// ---------------------------------------------------------------------------
#define B_     4096
#define NIN    2048
#define NOUT   2048
#define KTOT   4096              // NIN + NOUT
#define NTOT   8192              // 4 * NOUT

// GEMM tiling: 128(M) x 128(N-packed) x 64(K), 256 threads, 8 warps (4m x 2n),
// warp tile 32x64, 2 CTAs/SM, barrier hoisted before kk3's MMAs.
#define BM     128
#define BN     128
#define BK     64
#define STG    3
#define A_STAGE_B  (BM * BK * 2)             // 16384
#define B_STAGE_B  (BN * BK * 2)             // 16384
#define STAGE_B    (A_STAGE_B + B_STAGE_B)   // 32768
#define SMEM_TOTAL (STG * STAGE_B)           // 98304 -> 2 CTAs/SM
#define EPI_PITCH  132                        // fp32 words per row (128 + 4 pad)

// ---------------------------------------------------------------------------
// Device scratch (static; no allocation allowed)
// ---------------------------------------------------------------------------
__device__ __align__(16) __half g_Th[(size_t)B_ * KTOT];     // 32 MB
__device__ __align__(16) __half g_Wh[(size_t)NTOT * KTOT];   // 64 MB (rows: j*4+gate)

// ---------------------------------------------------------------------------
// Helpers
// ---------------------------------------------------------------------------
__device__ __forceinline__ uint32_t smem_u32(const void* p) {
    uint32_t a;
    asm("{ .reg .u64 t; cvta.to.shared.u64 t, %1; cvt.u32.u64 %0, t; }" : "=r"(a) : "l"(p));
    return a;
}

__device__ __forceinline__ void cp16(uint32_t dst, const void* src) {
    asm volatile("cp.async.cg.shared.global [%0], [%1], 16;" :: "r"(dst), "l"(src));
}

__device__ __forceinline__ void ldsm4(uint32_t* d, uint32_t addr) {
    asm volatile("ldmatrix.sync.aligned.m8n8.x4.shared.b16 {%0,%1,%2,%3}, [%4];"
                 : "=r"(d[0]), "=r"(d[1]), "=r"(d[2]), "=r"(d[3]) : "r"(addr));
}

__device__ __forceinline__ void mma16816(float* c,
                                         uint32_t a0, uint32_t a1, uint32_t a2, uint32_t a3,
                                         uint32_t b0, uint32_t b1) {
    asm volatile("mma.sync.aligned.m16n8k16.row.col.f32.f16.f16.f32 "
                 "{%0,%1,%2,%3}, {%4,%5,%6,%7}, {%8,%9}, {%0,%1,%2,%3};"
                 : "+f"(c[0]), "+f"(c[1]), "+f"(c[2]), "+f"(c[3])
                 : "r"(a0), "r"(a1), "r"(a2), "r"(a3), "r"(b0), "r"(b1));
}

__device__ __forceinline__ float sigmoidf_(float z) { return 1.0f / (1.0f + expf(-z)); }

__device__ __forceinline__ uint32_t packh2(float a, float b) {
    __half2 p = __floats2half2_rn(a, b);
    return *reinterpret_cast<uint32_t*>(&p);
}

// ---------------------------------------------------------------------------
// Fused conversion kernel: fp32 -> fp16, 2 independent uint4s per thread.
// Blocks [0, 4096): T rows (one row per block; lower half from x, upper from h).
// Blocks [4096, 12288): W rows (p = j*4 + gate), 2 chunks per thread.
// ---------------------------------------------------------------------------
__device__ __forceinline__ uint4 pack8_h(const float* src) {
    float4 v0 = *reinterpret_cast<const float4*>(src);
    float4 v1 = *reinterpret_cast<const float4*>(src + 4);
    uint4 o;
    o.x = packh2(v0.x, v0.y);
    o.y = packh2(v0.z, v0.w);
    o.z = packh2(v1.x, v1.y);
    o.w = packh2(v1.z, v1.w);
    return o;
}

#define T_BLOCKS2  B_                         // 4096 (one T row per block)
#define W_BLOCKS2  NTOT                       // 8192 (one W row per block)

__global__ void __launch_bounds__(256)
conv_all_kernel(const float* __restrict__ x, const float* __restrict__ h,
                const float* __restrict__ Wf, const float* __restrict__ Wi,
                const float* __restrict__ Wo, const float* __restrict__ Wg) {
    uint32_t b = blockIdx.x;
    uint32_t t = threadIdx.x;
    if (b < T_BLOCKS2) {
        // T row m = b: k1 = t*8 (< 2048 -> x), k2 = (t+256)*8 (>= 2048 -> h)
        uint32_t m = b;
        const float* s1 = x + (size_t)m * NIN + t * 8;
        const float* s2 = h + (size_t)m * NOUT + t * 8;     // (t+256)*8 - 2048
        uint4 v1 = pack8_h(s1);
        uint4 v2 = pack8_h(s2);
        __half* dst = g_Th + (size_t)m * KTOT;
        *reinterpret_cast<uint4*>(dst + t * 8)            = v1;
        *reinterpret_cast<uint4*>(dst + 2048 + t * 8)     = v2;
    } else {
        uint32_t jall = b - T_BLOCKS2;            // gate*2048 + j
        uint32_t gate = jall >> 11;
        uint32_t j = jall & 2047;
        const float* W = (gate == 0) ? Wf : (gate == 1) ? Wi : (gate == 2) ? Wo : Wg;
        uint32_t p = j * 4 + gate;
        const float* src = W + (size_t)j * KTOT;
        uint4 v1 = pack8_h(src + t * 8);
        uint4 v2 = pack8_h(src + 2048 + t * 8);
        __half* dst = g_Wh + (size_t)p * KTOT;
        *reinterpret_cast<uint4*>(dst + t * 8)        = v1;
        *reinterpret_cast<uint4*>(dst + 2048 + t * 8) = v2;
    }
}

// ---------------------------------------------------------------------------
// Fused GEMM + LSTM epilogue. Barrier hoisted: stg_cur's last read is the
// kk3 fragment load (issued during kk2), so wait_group + __syncthreads move
// BEFORE kk3's MMAs; kk3's 16 MMAs then overlap barrier skew and the
// next-stage kk0 LDSM chain (interleaved, in-place register reuse).
// grid = 2048 (mt = bid&31, nt = bid>>5), 256 threads, 3-stage cp.async.
// ---------------------------------------------------------------------------
__global__ void __launch_bounds__(256, 2)
lstm_gemm_fused_kernel(const float* __restrict__ c_old,
                       const float* __restrict__ bf,
                       const float* __restrict__ bi,
                       const float* __restrict__ bo,
                       const float* __restrict__ bg,
                       float* __restrict__ out) {
    extern __shared__ __align__(1024) char smem[];
    const uint32_t sbase = smem_u32(smem);

    const int t    = threadIdx.x;
    const int lane = t & 31;
    const int wid  = t >> 5;      // 0..7
    const int wm   = wid & 3;     // warp m band: 32 rows
    const int wn   = wid >> 2;    // warp n band: 64 packed cols

    const int bid = blockIdx.x;
    const int mt = bid & 31;
    const int nt = bid >> 5;
    const int m0 = mt * BM;
    const int p0 = nt * BN;       // packed col base
    const int j0 = nt * 32;       // j base

    // ---- cp.async constants
    const uint32_t xorvt  = (uint32_t)((t >> 3) & 7) << 4;
    const uint32_t dstA0  = (uint32_t)(t >> 3) * 128 + (((uint32_t)(t & 7) * 16) ^ xorvt);
    const uint32_t dstB0  = dstA0 + A_STAGE_B;
    const __half* srcA = g_Th + (size_t)(m0 + (t >> 3)) * KTOT + (t & 7) * 8;
    const __half* srcB = g_Wh + (size_t)(p0 + (t >> 3)) * KTOT + (t & 7) * 8;
    int kptr = 0;   // element offset bumped by BK per fill

    const uint32_t stg0 = sbase;
    const uint32_t stg1 = sbase + STAGE_B;
    const uint32_t stg2 = sbase + 2 * STAGE_B;

    // ---- LDSM constants: addr = stage + rowterm[f] + kxv[kk]
    const uint32_t lrow  = (uint32_t)(lane & 15);
    const uint32_t lkofb = (lane & 16) ? 16u : 0u;
    const uint32_t xorv  = (uint32_t)(lane & 7) << 4;
    uint32_t rowA[2], rowB[4], kxv[4];
#pragma unroll
    for (int mf = 0; mf < 2; mf++)
        rowA[mf] = (uint32_t)(wm * 32 + mf * 16 + lrow) * 128;
#pragma unroll
    for (int nf = 0; nf < 4; nf++)
        rowB[nf] = A_STAGE_B + (uint32_t)(wn * 64 + nf * 16 + lrow) * 128;
#pragma unroll
    for (int kk = 0; kk < 4; kk++)
        kxv[kk] = ((uint32_t)(kk * 32) + lkofb) ^ xorv;

    float acc[2][8][4];           // [mf][n8][quad]
#pragma unroll
    for (int i = 0; i < 2; i++)
#pragma unroll
        for (int j = 0; j < 8; j++)
#pragma unroll
            for (int q = 0; q < 4; q++) acc[i][j][q] = 0.0f;

    uint32_t a[2][4], b[4][4];

    auto fill_stage = [&](uint32_t stg) {
        const __half* sa = srcA + kptr;
        const __half* sb = srcB + kptr;
#pragma unroll
        for (int i = 0; i < 4; i++)
            cp16(stg + dstA0 + i * 4096, sa + (size_t)i * 32 * KTOT);
#pragma unroll
        for (int i = 0; i < 4; i++)
            cp16(stg + dstB0 + i * 4096, sb + (size_t)i * 32 * KTOT);
        asm volatile("cp.async.commit_group;" ::: "memory");
        kptr += BK;
    };

    auto load_kk = [&](uint32_t stg, int kk) {
        const uint32_t kx = kxv[kk];
#pragma unroll
        for (int mf = 0; mf < 2; mf++)
            ldsm4(a[mf], stg + rowA[mf] + kx);
#pragma unroll
        for (int nf = 0; nf < 4; nf++)
            ldsm4(b[nf], stg + rowB[nf] + kx);
    };

    auto mma_all = [&]() {
#pragma unroll
        for (int nf = 0; nf < 4; nf++) {
#pragma unroll
            for (int mf = 0; mf < 2; mf++) {
                mma16816(acc[mf][nf * 2],     a[mf][0], a[mf][1], a[mf][2], a[mf][3],
                         b[nf][0], b[nf][2]);
                mma16816(acc[mf][nf * 2 + 1], a[mf][0], a[mf][1], a[mf][2], a[mf][3],
                         b[nf][1], b[nf][3]);
            }
        }
    };

    // ---- prologue: two stages in flight; wait -> BARRIER -> preload kk0
    fill_stage(stg0);
    fill_stage(stg1);
    asm volatile("cp.async.wait_group 1;" ::: "memory");
    __syncthreads();
    load_kk(stg0, 0);

    const int NIT = KTOT / BK;     // 64
    uint32_t stg_cur = stg0, stg_nxt = stg1, stg_fill = stg2;

    for (int it = 0; it < NIT; it++) {
        // fill(it+2): buffer released by the barrier inside iter it-1.
        if (it + 2 < NIT)
            fill_stage(stg_fill);

        // kk0..kk2 MMAs; each followed by next-kk fragment loads.
        mma_all();                         // kk0
        load_kk(stg_cur, 1);
        mma_all();                         // kk1
        load_kk(stg_cur, 2);
        mma_all();                         // kk2
        load_kk(stg_cur, 3);               // last read of stg_cur

        if (it + 1 < NIT) {
            // barrier hoisted before kk3's MMAs
            if (it + 2 < NIT)
                asm volatile("cp.async.wait_group 1;" ::: "memory");
            else
                asm volatile("cp.async.wait_group 0;" ::: "memory");
            __syncthreads();

            // kk3 MMAs interleaved with next-stage kk0 loads (in-place regs)
#pragma unroll
            for (int nf = 0; nf < 4; nf++) {
                mma16816(acc[0][nf * 2],     a[0][0], a[0][1], a[0][2], a[0][3],
                         b[nf][0], b[nf][2]);
                mma16816(acc[0][nf * 2 + 1], a[0][0], a[0][1], a[0][2], a[0][3],
                         b[nf][1], b[nf][3]);
            }
            ldsm4(a[0], stg_nxt + rowA[0] + kxv[0]);
#pragma unroll
            for (int nf = 0; nf < 4; nf++) {
                mma16816(acc[1][nf * 2],     a[1][0], a[1][1], a[1][2], a[1][3],
                         b[nf][0], b[nf][2]);
                mma16816(acc[1][nf * 2 + 1], a[1][0], a[1][1], a[1][2], a[1][3],
                         b[nf][1], b[nf][3]);
                ldsm4(b[nf], stg_nxt + rowB[nf] + kxv[0]);
            }
            ldsm4(a[1], stg_nxt + rowA[1] + kxv[0]);
        } else {
            mma_all();                     // final kk3
        }

        uint32_t tmp = stg_cur;
        stg_cur = stg_nxt;
        stg_nxt = stg_fill;
        stg_fill = tmp;
    }

    // ---- drain, then reuse smem as fp32 Z tile [128][EPI_PITCH] ----
    asm volatile("cp.async.wait_group 0;" ::: "memory");
    __syncthreads();

    float* zt = reinterpret_cast<float*>(smem);
    {
        const int r0 = wm * 32 + (lane >> 2);
        const int c0 = wn * 64 + (lane & 3) * 2;
#pragma unroll
        for (int mf = 0; mf < 2; mf++) {
            int row = r0 + mf * 16;
#pragma unroll
            for (int n8 = 0; n8 < 8; n8++) {
                int pc = c0 + n8 * 8;
                *reinterpret_cast<float2*>(&zt[(size_t)row * EPI_PITCH + pc]) =
                    make_float2(acc[mf][n8][0], acc[mf][n8][1]);
                *reinterpret_cast<float2*>(&zt[(size_t)(row + 8) * EPI_PITCH + pc]) =
                    make_float2(acc[mf][n8][2], acc[mf][n8][3]);
            }
        }
    }
    __syncthreads();

    // ---- fused LSTM epilogue: warp -> 16-row block, lane -> j ----
    {
        const int j = lane;                  // 0..31
        const int jg = j0 + j;
        const float bfs = bf[jg];
        const float bis = bi[jg];
        const float bos = bo[jg];
        const float bgs = bg[jg];
#pragma unroll
        for (int i = 0; i < 16; i++) {
            int ml = wid * 16 + i;
            float4 z = *reinterpret_cast<const float4*>(&zt[(size_t)ml * EPI_PITCH + j * 4]);
            float zf = z.x + bfs;
            float zi = z.y + bis;
            float zo = z.z + bos;
            float zg = z.w + bgs;
            int m = m0 + ml;
            float co = c_old[(size_t)m * NOUT + jg];
            float f  = sigmoidf_(zf);
            float ii = sigmoidf_(zi);
            float oo = sigmoidf_(zo);
            float g  = tanhf(zg);
            float c  = f * co + ii * g;
            float hh = oo * tanhf(c);
            out[(size_t)m * NOUT + jg] = c;
            out[(size_t)B_ * NOUT + (size_t)m * NOUT + jg] = hh;
        }
    }
}

// ---------------------------------------------------------------------------
// kernel_launch
// Input order: c_old, h_old, x, Wf, bf, Wi, bi, Wo, bo, Wg, bg, mode
// ---------------------------------------------------------------------------
extern "C" void kernel_launch(void* const* d_in, const int* in_sizes, int n_in,
                              void* d_out, int out_size) {
    const float* c_old = (const float*)d_in[0];
    const float* h_old = (const float*)d_in[1];
    const float* x     = (const float*)d_in[2];
    const float* Wf    = (const float*)d_in[3];
    const float* bf    = (const float*)d_in[4];
    const float* Wi    = (const float*)d_in[5];
    const float* bi    = (const float*)d_in[6];
    const float* Wo    = (const float*)d_in[7];
    const float* bo    = (const float*)d_in[8];
    const float* Wg    = (const float*)d_in[9];
    const float* bg    = (const float*)d_in[10];
    float* out = (float*)d_out;

    static int configured = 0;
    if (!configured) {
        cudaFuncSetAttribute(lstm_gemm_fused_kernel,
                             cudaFuncAttributeMaxDynamicSharedMemorySize, SMEM_TOTAL);
        configured = 1;
    }

    conv_all_kernel<<<T_BLOCKS2 + W_BLOCKS2, 256>>>(x, h_old, Wf, Wi, Wo, Wg);

    lstm_gemm_fused_kernel<<<(B_ / BM) * (NTOT / BN), 256, SMEM_TOTAL>>>(
        c_old, bf, bi, bo, bg, out);
}